// round 15
// baseline (speedup 1.0000x reference)
#include <cuda_runtime.h>
#include <cuda_bf16.h>

#define EPSV 1e-5f
#define LOG2E 1.4426950408889634f

// ---------------- scratch (device globals; no cudaMalloc allowed) ----------
__device__ __nv_bfloat16 d_Fh[8 * 1024 * 32];    // f*log2e: [b][n=1024][k=32]
__device__ __nv_bfloat16 d_Ght[8 * 4096 * 32];   // g^T:[b][m=4096][k=32]
__device__ __nv_bfloat16 d_Hh[8 * 128 * 1024];   // hh: [b][c=128][n=1024]
__device__ __nv_bfloat16 d_Ot[8 * 4096 * 128];   // o^T:[b][m=4096][c=128] (bf16)

__device__ __nv_bfloat16 d_Wc[192 * 256];        // BN-folded W for conv1|2|3 (oc-major)
__device__ float d_Bc[192];                      // folded biases conv1|2|3
__device__ __nv_bfloat16 d_W4h[256 * 128];       // BN-folded W4
__device__ float d_B4[256];                      // folded bias conv4

// ---------------- mma / ldmatrix / cp.async helpers -------------------------
__device__ __forceinline__ void mma_bf16(float c[4], unsigned a0, unsigned a1,
                                         unsigned a2, unsigned a3,
                                         unsigned b0, unsigned b1) {
    asm volatile(
        "mma.sync.aligned.m16n8k16.row.col.f32.bf16.bf16.f32 "
        "{%0,%1,%2,%3}, {%4,%5,%6,%7}, {%8,%9}, {%0,%1,%2,%3};"
        : "+f"(c[0]), "+f"(c[1]), "+f"(c[2]), "+f"(c[3])
        : "r"(a0), "r"(a1), "r"(a2), "r"(a3), "r"(b0), "r"(b1));
}
__device__ __forceinline__ unsigned smem_u32(const void* p) {
    return (unsigned)__cvta_generic_to_shared(p);
}
__device__ __forceinline__ void ldsm_x4(unsigned& r0, unsigned& r1, unsigned& r2,
                                        unsigned& r3, unsigned addr) {
    asm volatile("ldmatrix.sync.aligned.m8n8.x4.shared.b16 {%0,%1,%2,%3}, [%4];"
                 : "=r"(r0), "=r"(r1), "=r"(r2), "=r"(r3) : "r"(addr));
}
__device__ __forceinline__ void ldsm_x2t(unsigned& r0, unsigned& r1, unsigned addr) {
    asm volatile("ldmatrix.sync.aligned.m8n8.x2.trans.shared.b16 {%0,%1}, [%2];"
                 : "=r"(r0), "=r"(r1) : "r"(addr));
}
__device__ __forceinline__ unsigned bf2u(float a, float b) {
    __nv_bfloat162 h = __floats2bfloat162_rn(a, b);
    return *(unsigned*)&h;
}
__device__ __forceinline__ float ex2(float x) {
    float y;
    asm("ex2.approx.ftz.f32 %0, %1;" : "=f"(y) : "f"(x));
    return y;
}
__device__ __forceinline__ void cp16(void* dst, const void* src) {
    asm volatile("cp.async.ca.shared.global [%0], [%1], 16;\n"
                 :: "r"(smem_u32(dst)), "l"(src));
}
__device__ __forceinline__ void cp_commit() {
    asm volatile("cp.async.commit_group;\n" ::: "memory");
}
__device__ __forceinline__ void cp_wait0() {
    asm volatile("cp.async.wait_group 0;\n" ::: "memory");
}
__device__ __forceinline__ void cp_wait1() {
    asm volatile("cp.async.wait_group 1;\n" ::: "memory");
}

// ---------------------------------------------------------------------------
// prep v2: one (row, 16-col segment) per thread; single rsqrt per thread.
// ---------------------------------------------------------------------------
__global__ void __launch_bounds__(256) prep_kernel(
    const float* __restrict__ w1, const float* __restrict__ b1,
    const float* __restrict__ s1, const float* __restrict__ t1,
    const float* __restrict__ m1, const float* __restrict__ v1,
    const float* __restrict__ w2, const float* __restrict__ b2,
    const float* __restrict__ s2, const float* __restrict__ t2,
    const float* __restrict__ m2, const float* __restrict__ v2,
    const float* __restrict__ w3, const float* __restrict__ b3,
    const float* __restrict__ s3, const float* __restrict__ t3,
    const float* __restrict__ m3, const float* __restrict__ v3,
    const float* __restrict__ w4, const float* __restrict__ b4,
    const float* __restrict__ s4, const float* __restrict__ t4,
    const float* __restrict__ m4, const float* __restrict__ v4)
{
    int gid = blockIdx.x * 256 + threadIdx.x;

    if (gid < 3072) {
        int row = gid >> 4, seg = (gid & 15) * 16;
        const float* wsrc;
        float al;
        if (row < 32) {
            al = s1[row] * rsqrtf(v1[row] + EPSV);
            wsrc = w1 + row * 256;
        } else if (row < 64) {
            int o = row - 32;
            al = s2[o] * rsqrtf(v2[o] + EPSV);
            wsrc = w2 + o * 256;
        } else {
            int o = row - 64;
            al = s3[o] * rsqrtf(v3[o] + EPSV);
            wsrc = w3 + o * 256;
        }
        __nv_bfloat16 ov[16];
#pragma unroll
        for (int j = 0; j < 16; j++)
            ov[j] = __float2bfloat16_rn(wsrc[seg + j] * al);
        *(uint4*)(d_Wc + row * 256 + seg) = *(uint4*)&ov[0];
        *(uint4*)(d_Wc + row * 256 + seg + 8) = *(uint4*)&ov[8];
    } else if (gid < 5120) {
        int i2 = gid - 3072;
        int row = i2 >> 3, seg = (i2 & 7) * 16;
        float al = s4[row] * rsqrtf(v4[row] + EPSV);
        const float* wsrc = w4 + row * 128;
        __nv_bfloat16 ov[16];
#pragma unroll
        for (int j = 0; j < 16; j++)
            ov[j] = __float2bfloat16_rn(wsrc[seg + j] * al);
        *(uint4*)(d_W4h + row * 128 + seg) = *(uint4*)&ov[0];
        *(uint4*)(d_W4h + row * 128 + seg + 8) = *(uint4*)&ov[8];
    } else if (gid < 5568) {
        int oc = gid - 5120;
        if (oc < 192) {
            float al, bb;
            if (oc < 32) {
                al = s1[oc] * rsqrtf(v1[oc] + EPSV);
                bb = (b1[oc] - m1[oc]) * al + t1[oc];
            } else if (oc < 64) {
                int o = oc - 32;
                al = s2[o] * rsqrtf(v2[o] + EPSV);
                bb = (b2[o] - m2[o]) * al + t2[o];
            } else {
                int o = oc - 64;
                al = s3[o] * rsqrtf(v3[o] + EPSV);
                bb = (b3[o] - m3[o]) * al + t3[o];
            }
            d_Bc[oc] = bb;
        } else {
            int o = oc - 192;
            float al = s4[o] * rsqrtf(v4[o] + EPSV);
            d_B4[o] = (b4[o] - m4[o]) * al + t4[o];
        }
    }
}

// ---------------------------------------------------------------------------
// Fused conv1+2+3 via tensor cores. d_Fh output pre-scaled by log2(e).
// ---------------------------------------------------------------------------
__global__ void __launch_bounds__(512) conv123_kernel(const float* __restrict__ x)
{
    __shared__ __align__(16) char sm[45056];
    __nv_bfloat16* Xs = (__nv_bfloat16*)sm;             // [64][136]
    __nv_bfloat16* Ws = (__nv_bfloat16*)(sm + 17408);   // [192][72]
    __nv_bfloat16* HP1 = (__nv_bfloat16*)sm;            // [32][64]  (epilogue)
    __nv_bfloat16* HP3 = (__nv_bfloat16*)(sm + 4096);   // [128][64] (epilogue)
    __nv_bfloat16* Gt  = (__nv_bfloat16*)(sm + 20480);  // [128][40] (epilogue)

    const int b = blockIdx.y, r = blockIdx.x, t = threadIdx.x;
    const int lane = t & 31, wid = t >> 5;
    const int g = lane >> 2, t4 = lane & 3;
    const int oc0w = (wid & 3) * 48, m0w = (wid >> 2) * 32;

    const float* xb = x + (size_t)b * 1048576 + (size_t)r * 128;

    float c[3][4][4];
#pragma unroll
    for (int i = 0; i < 3; i++)
#pragma unroll
        for (int j = 0; j < 4; j++)
#pragma unroll
            for (int e = 0; e < 4; e++) c[i][j][e] = 0.f;

    for (int kc = 0; kc < 256; kc += 64) {
        __syncthreads();
#pragma unroll
        for (int j = 0; j < 4; j++) {
            int i = t + j * 512;
            int row = i >> 5, col4 = i & 31;
            float4 v = *(const float4*)(xb + (size_t)(kc + row) * 4096 + col4 * 4);
            uint2 u;
            u.x = bf2u(v.x, v.y);
            u.y = bf2u(v.z, v.w);
            *(uint2*)(Xs + row * 136 + col4 * 4) = u;
        }
#pragma unroll
        for (int j = 0; j < 3; j++) {
            int i = t + j * 512;
            int row = i >> 3, part = i & 7;
            *(uint4*)(Ws + row * 72 + part * 8) =
                *(const uint4*)(d_Wc + row * 256 + kc + part * 8);
        }
        __syncthreads();

#pragma unroll
        for (int ks = 0; ks < 4; ks++) {
            int k0 = ks * 16;
            unsigned a[3][4];
#pragma unroll
            for (int mt = 0; mt < 3; mt++) {
                unsigned addr = smem_u32(Ws + (oc0w + mt * 16 + (lane & 15)) * 72 +
                                         k0 + ((lane >> 4) << 3));
                ldsm_x4(a[mt][0], a[mt][1], a[mt][2], a[mt][3], addr);
            }
#pragma unroll
            for (int nt = 0; nt < 4; nt++) {
                unsigned b0, b1;
                unsigned addr = smem_u32(Xs + (k0 + (lane & 15)) * 136 + m0w + nt * 8);
                ldsm_x2t(b0, b1, addr);
#pragma unroll
                for (int mt = 0; mt < 3; mt++)
                    mma_bf16(c[mt][nt], a[mt][0], a[mt][1], a[mt][2], a[mt][3], b0, b1);
            }
        }
    }
    __syncthreads();

#pragma unroll
    for (int mt = 0; mt < 3; mt++) {
        int ocb = oc0w + mt * 16;
        float bg  = d_Bc[ocb + g];
        float bg8 = d_Bc[ocb + 8 + g];
#pragma unroll
        for (int nt = 0; nt < 4; nt++) {
            int mloc = m0w + nt * 8 + 2 * t4;
            int rh = mloc >> 6, cp = (mloc & 63) >> 1;
            float v0 = fmaxf(c[mt][nt][0] + bg, 0.f);
            float v1 = fmaxf(c[mt][nt][1] + bg, 0.f);
            float v2 = fmaxf(c[mt][nt][2] + bg8, 0.f);
            float v3 = fmaxf(c[mt][nt][3] + bg8, 0.f);
            if (ocb < 32) {
                HP1[(ocb + g) * 64 + rh * 32 + cp]     = __float2bfloat16_rn(fmaxf(v0, v1));
                HP1[(ocb + 8 + g) * 64 + rh * 32 + cp] = __float2bfloat16_rn(fmaxf(v2, v3));
            } else if (ocb < 64) {
                int oc = ocb - 32 + g;
                Gt[mloc * 40 + oc]           = __float2bfloat16_rn(v0);
                Gt[(mloc + 1) * 40 + oc]     = __float2bfloat16_rn(v1);
                Gt[mloc * 40 + oc + 8]       = __float2bfloat16_rn(v2);
                Gt[(mloc + 1) * 40 + oc + 8] = __float2bfloat16_rn(v3);
            } else {
                HP3[(ocb - 64 + g) * 64 + rh * 32 + cp]     = __float2bfloat16_rn(fmaxf(v0, v1));
                HP3[(ocb - 64 + 8 + g) * 64 + rh * 32 + cp] = __float2bfloat16_rn(fmaxf(v2, v3));
            }
        }
    }
    __syncthreads();

    {   // d_Fh: 32 n x 32 oc, scaled by log2(e) for base-2 softmax
        int cp = t >> 4, oc0 = (t & 15) * 2;
        float f0 = __bfloat162float(__hmax(HP1[oc0 * 64 + cp], HP1[oc0 * 64 + 32 + cp]));
        float f1 = __bfloat162float(__hmax(HP1[(oc0 + 1) * 64 + cp], HP1[(oc0 + 1) * 64 + 32 + cp]));
        __nv_bfloat162 h = __floats2bfloat162_rn(f0 * LOG2E, f1 * LOG2E);
        *(__nv_bfloat162*)(d_Fh + (size_t)b * 32768 + (size_t)(r * 32 + cp) * 32 + oc0) = h;
    }
    {   // d_Hh: 128 c x 32 n
        int cc = t >> 2, q = (t & 3) * 8;
        __nv_bfloat16 out8[8];
#pragma unroll
        for (int jj = 0; jj < 8; jj++)
            out8[jj] = __hmax(HP3[cc * 64 + q + jj], HP3[cc * 64 + 32 + q + jj]);
        *(uint4*)(d_Hh + (size_t)b * 131072 + (size_t)cc * 1024 + r * 32 + q) =
            *(uint4*)out8;
    }
    {   // d_Ght: 128 m x 32 k
        int row = t >> 2, part = t & 3;
        *(uint4*)(d_Ght + (size_t)b * 131072 + (size_t)(r * 128 + row) * 32 + part * 8) =
            *(uint4*)(Gt + row * 40 + part * 8);
    }
}

// ---------------------------------------------------------------------------
// Flash attention v3 + cp.async double-buffered staging; base-2 softmax (ex2).
// Dynamic smem: Gs [0,10240), buf0 {Fs,Vs} [10240,33792), buf1 [33792,57344).
// ---------------------------------------------------------------------------
__device__ __forceinline__ void stage_attn_chunk(
    __nv_bfloat16* Fs, __nv_bfloat16* Vs,
    const __nv_bfloat16* fB, const __nv_bfloat16* hB, int n0, int t)
{
    {
        int row = t >> 2, part = t & 3;
        cp16(Fs + row * 40 + part * 8, fB + (size_t)(n0 + row) * 32 + part * 8);
    }
    {
        int cpos = t >> 1, nq = (t & 1) * 32;
        const __nv_bfloat16* src = hB + (size_t)cpos * 1024 + n0 + nq;
#pragma unroll
        for (int j = 0; j < 4; j++)
            cp16(Vs + cpos * 72 + nq + j * 8, src + j * 8);
    }
}

__global__ void __launch_bounds__(256, 2) attn_kernel()
{
    extern __shared__ __align__(16) char smd[];
    __nv_bfloat16* Gs  = (__nv_bfloat16*)smd;
    __nv_bfloat16* Fsb[2] = { (__nv_bfloat16*)(smd + 10240),
                              (__nv_bfloat16*)(smd + 33792) };
    __nv_bfloat16* Vsb[2] = { (__nv_bfloat16*)(smd + 15360),
                              (__nv_bfloat16*)(smd + 38912) };

    const int b = blockIdx.y;
    const int m0 = blockIdx.x * 128;
    const int t = threadIdx.x;
    const int lane = t & 31, wid = t >> 5;
    const int g = lane >> 2, t4 = lane & 3;
    const int q = lane & 7, sel = lane >> 3;

    const __nv_bfloat16* gB = d_Ght + (size_t)b * 131072;
    const __nv_bfloat16* fB = d_Fh + (size_t)b * 32768;
    const __nv_bfloat16* hB = d_Hh + (size_t)b * 131072;

    stage_attn_chunk(Fsb[0], Vsb[0], fB, hB, 0, t);
    cp_commit();

#pragma unroll
    for (int j = 0; j < 2; j++) {
        int i = t + j * 256;
        int row = i >> 2, part = i & 3;
        *(uint4*)&Gs[row * 40 + part * 8] =
            *(const uint4*)(gB + (size_t)(m0 + row) * 32 + part * 8);
    }
    __syncthreads();

    unsigned ag[2][4];
#pragma unroll
    for (int kt = 0; kt < 2; kt++) {
        unsigned addr = smem_u32(Gs + (wid * 16 + (lane & 15)) * 40 +
                                 kt * 16 + ((lane >> 4) << 3));
        ldsm_x4(ag[kt][0], ag[kt][1], ag[kt][2], ag[kt][3], addr);
    }

    float o[16][4];
#pragma unroll
    for (int i = 0; i < 16; i++)
#pragma unroll
        for (int e = 0; e < 4; e++) o[i][e] = 0.f;
    float rm0 = -1e30f, rm1 = -1e30f, rs0 = 0.f, rs1 = 0.f;

    for (int it = 0; it < 16; it++) {
        const int cur = it & 1;
        if (it < 15) {
            stage_attn_chunk(Fsb[cur ^ 1], Vsb[cur ^ 1], fB, hB, (it + 1) * 64, t);
            cp_commit();
            cp_wait1();
        } else {
            cp_wait0();
        }
        __syncthreads();

        const __nv_bfloat16* Fs = Fsb[cur];
        const __nv_bfloat16* Vs = Vsb[cur];

        // ---- GEMM1: S2[16m][64n] per warp (base-2 scaled scores) ----
        float sc[8][4];
#pragma unroll
        for (int nt = 0; nt < 8; nt++)
#pragma unroll
            for (int e = 0; e < 4; e++) sc[nt][e] = 0.f;
#pragma unroll
        for (int kt = 0; kt < 2; kt++)
#pragma unroll
            for (int ntp = 0; ntp < 4; ntp++) {
                unsigned b00, b01, b10, b11;
                unsigned addr = smem_u32(Fs + (ntp * 16 + (sel >> 1) * 8 + q) * 40 +
                                         kt * 16 + (sel & 1) * 8);
                ldsm_x4(b00, b01, b10, b11, addr);
                mma_bf16(sc[ntp * 2],     ag[kt][0], ag[kt][1], ag[kt][2], ag[kt][3], b00, b01);
                mma_bf16(sc[ntp * 2 + 1], ag[kt][0], ag[kt][1], ag[kt][2], ag[kt][3], b10, b11);
            }

        // ---- in-register online softmax (base 2; rows g, g+8) ----
        float cm0 = -1e30f, cm1 = -1e30f;
#pragma unroll
        for (int nt = 0; nt < 8; nt++) {
            cm0 = fmaxf(cm0, fmaxf(sc[nt][0], sc[nt][1]));
            cm1 = fmaxf(cm1, fmaxf(sc[nt][2], sc[nt][3]));
        }
        cm0 = fmaxf(cm0, __shfl_xor_sync(0xffffffffu, cm0, 1));
        cm0 = fmaxf(cm0, __shfl_xor_sync(0xffffffffu, cm0, 2));
        cm1 = fmaxf(cm1, __shfl_xor_sync(0xffffffffu, cm1, 1));
        cm1 = fmaxf(cm1, __shfl_xor_sync(0xffffffffu, cm1, 2));
        float nm0 = fmaxf(rm0, cm0), nm1 = fmaxf(rm1, cm1);
        float scl0 = ex2(rm0 - nm0), scl1 = ex2(rm1 - nm1);
        rm0 = nm0; rm1 = nm1;
        rs0 *= scl0; rs1 *= scl1;

        unsigned pa[4][4];
        float s0a = 0.f, s1a = 0.f;
#pragma unroll
        for (int kt2 = 0; kt2 < 4; kt2++) {
            float e00 = ex2(sc[2 * kt2][0] - nm0);
            float e01 = ex2(sc[2 * kt2][1] - nm0);
            float e02 = ex2(sc[2 * kt2][2] - nm1);
            float e03 = ex2(sc[2 * kt2][3] - nm1);
            float e10 = ex2(sc[2 * kt2 + 1][0] - nm0);
            float e11 = ex2(sc[2 * kt2 + 1][1] - nm0);
            float e12 = ex2(sc[2 * kt2 + 1][2] - nm1);
            float e13 = ex2(sc[2 * kt2 + 1][3] - nm1);
            pa[kt2][0] = bf2u(e00, e01);
            pa[kt2][1] = bf2u(e02, e03);
            pa[kt2][2] = bf2u(e10, e11);
            pa[kt2][3] = bf2u(e12, e13);
            s0a += e00 + e01 + e10 + e11;
            s1a += e02 + e03 + e12 + e13;
        }
        rs0 += s0a; rs1 += s1a;

#pragma unroll
        for (int ct = 0; ct < 16; ct++) {
            o[ct][0] *= scl0; o[ct][1] *= scl0;
            o[ct][2] *= scl1; o[ct][3] *= scl1;
        }

        // ---- GEMM2: O[16m][128c] += P . V^T ----
#pragma unroll
        for (int kt2 = 0; kt2 < 4; kt2++)
#pragma unroll
            for (int cg2 = 0; cg2 < 8; cg2++) {
                unsigned b00, b01, b10, b11;
                unsigned addr = smem_u32(Vs + (cg2 * 16 + (sel >> 1) * 8 + q) * 72 +
                                         kt2 * 16 + (sel & 1) * 8);
                ldsm_x4(b00, b01, b10, b11, addr);
                mma_bf16(o[cg2 * 2],     pa[kt2][0], pa[kt2][1], pa[kt2][2], pa[kt2][3], b00, b01);
                mma_bf16(o[cg2 * 2 + 1], pa[kt2][0], pa[kt2][1], pa[kt2][2], pa[kt2][3], b10, b11);
            }
        __syncthreads();
    }

    // ---- normalize + store bf16 O[m][c] ----
    rs0 += __shfl_xor_sync(0xffffffffu, rs0, 1);
    rs0 += __shfl_xor_sync(0xffffffffu, rs0, 2);
    rs1 += __shfl_xor_sync(0xffffffffu, rs1, 1);
    rs1 += __shfl_xor_sync(0xffffffffu, rs1, 2);
    float inv0 = 1.f / rs0, inv1 = 1.f / rs1;

    __nv_bfloat16* oB = d_Ot + (size_t)b * 524288;
    int row0 = m0 + wid * 16 + g;
#pragma unroll
    for (int ct = 0; ct < 16; ct++) {
        int cc = ct * 8 + 2 * t4;
        *(__nv_bfloat162*)(oB + (size_t)row0 * 128 + cc) =
            __floats2bfloat162_rn(o[ct][0] * inv0, o[ct][1] * inv0);
        *(__nv_bfloat162*)(oB + (size_t)(row0 + 8) * 128 + cc) =
            __floats2bfloat162_rn(o[ct][2] * inv1, o[ct][3] * inv1);
    }
}

// ---------------------------------------------------------------------------
// conv4 v3: C[64 oc][128 m] per block, K=128 staged once (cp.async).
// grid (32 m-tiles, 4 oc-tiles, 8 b) = 1024 blocks, 256 threads, ~3 blocks/SM.
// ---------------------------------------------------------------------------
__global__ void __launch_bounds__(256) conv4_kernel(
    const float* __restrict__ x, const float* __restrict__ gamma,
    float* __restrict__ out)
{
    extern __shared__ __align__(16) char smd[];
    __nv_bfloat16* Ots = (__nv_bfloat16*)smd;            // [128 m][136] (128 c)
    __nv_bfloat16* W4s = (__nv_bfloat16*)(smd + 34816);  // [64 oc][136] (128 c)

    const int b = blockIdx.z, OC0 = blockIdx.y * 64, pos0 = blockIdx.x * 128;
    const int t = threadIdx.x;
    const int lane = t & 31, wid = t >> 5;
    const int g = lane >> 2, t4 = lane & 3;
    const int q = lane & 7, sel = lane >> 3;
    const int oc0w = (wid & 3) * 16, m0w = (wid >> 2) * 64;

    // stage entire K (128 c) for both operands
    {
        int row = t >> 1, cq = (t & 1) * 64;
        const __nv_bfloat16* osrc =
            d_Ot + ((size_t)b * 4096 + pos0 + row) * 128 + cq;
#pragma unroll
        for (int j = 0; j < 8; j++)
            cp16(Ots + row * 136 + cq + j * 8, osrc + j * 8);
    }
    {
        int row = t >> 2, cq = (t & 3) * 32;
        const __nv_bfloat16* wsrc = d_W4h + (size_t)(OC0 + row) * 128 + cq;
#pragma unroll
        for (int j = 0; j < 4; j++)
            cp16(W4s + row * 136 + cq + j * 8, wsrc + j * 8);
    }
    cp_commit();

    float c[8][4];
#pragma unroll
    for (int j = 0; j < 8; j++)
#pragma unroll
        for (int e = 0; e < 4; e++) c[j][e] = 0.f;

    cp_wait0();
    __syncthreads();

#pragma unroll
    for (int ks = 0; ks < 8; ks++) {
        int k0 = ks * 16;
        unsigned a0, a1, a2, a3;
        {
            unsigned addr = smem_u32(W4s + (oc0w + (lane & 15)) * 136 +
                                     k0 + ((lane >> 4) << 3));
            ldsm_x4(a0, a1, a2, a3, addr);
        }
#pragma unroll
        for (int mgp = 0; mgp < 4; mgp++) {
            unsigned b00, b01, b10, b11;
            unsigned addr = smem_u32(Ots + (m0w + mgp * 16 + (sel >> 1) * 8 + q) * 136 +
                                     k0 + (sel & 1) * 8);
            ldsm_x4(b00, b01, b10, b11, addr);
            mma_bf16(c[mgp * 2],     a0, a1, a2, a3, b00, b01);
            mma_bf16(c[mgp * 2 + 1], a0, a1, a2, a3, b10, b11);
        }
    }

    float gm = *gamma;
    {
        int ocA = OC0 + oc0w + g;
        int ocB = ocA + 8;
        float bA = d_B4[ocA], bB = d_B4[ocB];
        size_t baseA = (size_t)b * 1048576 + (size_t)ocA * 4096 + pos0 + m0w;
        size_t baseB = (size_t)b * 1048576 + (size_t)ocB * 4096 + pos0 + m0w;
#pragma unroll
        for (int nt = 0; nt < 8; nt++) {
            int moff = nt * 8 + 2 * t4;
            float2 xa = *(const float2*)(x + baseA + moff);
            float2 ra;
            ra.x = gm * (c[nt][0] + bA) + xa.x;
            ra.y = gm * (c[nt][1] + bA) + xa.y;
            *(float2*)(out + baseA + moff) = ra;
            float2 xb = *(const float2*)(x + baseB + moff);
            float2 rb;
            rb.x = gm * (c[nt][2] + bB) + xb.x;
            rb.y = gm * (c[nt][3] + bB) + xb.y;
            *(float2*)(out + baseB + moff) = rb;
        }
    }
}

// ---------------------------------------------------------------------------
extern "C" void kernel_launch(void* const* d_in, const int* in_sizes, int n_in,
                              void* d_out, int out_size)
{
    const float* x = (const float*)d_in[0];
    const float* w1 = (const float*)d_in[1];
    const float* b1 = (const float*)d_in[2];
    const float* s1 = (const float*)d_in[3];
    const float* t1 = (const float*)d_in[4];
    const float* m1 = (const float*)d_in[5];
    const float* v1 = (const float*)d_in[6];
    const float* w2 = (const float*)d_in[7];
    const float* b2 = (const float*)d_in[8];
    const float* s2 = (const float*)d_in[9];
    const float* t2 = (const float*)d_in[10];
    const float* m2 = (const float*)d_in[11];
    const float* v2 = (const float*)d_in[12];
    const float* w3 = (const float*)d_in[13];
    const float* b3 = (const float*)d_in[14];
    const float* s3 = (const float*)d_in[15];
    const float* t3 = (const float*)d_in[16];
    const float* m3 = (const float*)d_in[17];
    const float* v3 = (const float*)d_in[18];
    const float* w4 = (const float*)d_in[19];
    const float* b4 = (const float*)d_in[20];
    const float* s4 = (const float*)d_in[21];
    const float* t4 = (const float*)d_in[22];
    const float* m4 = (const float*)d_in[23];
    const float* v4 = (const float*)d_in[24];
    const float* gamma = (const float*)d_in[25];

    cudaFuncSetAttribute(attn_kernel,
                         cudaFuncAttributeMaxDynamicSharedMemorySize, 57344);
    cudaFuncSetAttribute(conv4_kernel,
                         cudaFuncAttributeMaxDynamicSharedMemorySize, 52224);

    prep_kernel<<<22, 256>>>(w1, b1, s1, t1, m1, v1,
                             w2, b2, s2, t2, m2, v2,
                             w3, b3, s3, t3, m3, v3,
                             w4, b4, s4, t4, m4, v4);
    conv123_kernel<<<dim3(32, 8), 512>>>(x);
    attn_kernel<<<dim3(32, 8), 256, 57344>>>();
    conv4_kernel<<<dim3(32, 4, 8), 256, 52224>>>(x, gamma, (float*)d_out);
}

// round 16
// speedup vs baseline: 1.0870x; 1.0870x over previous
#include <cuda_runtime.h>
#include <cuda_bf16.h>

#define EPSV 1e-5f
#define LOG2E 1.4426950408889634f

// ---------------- scratch (device globals; no cudaMalloc allowed) ----------
__device__ __nv_bfloat16 d_Fh[8 * 1024 * 32];    // f*log2e: [b][n=1024][k=32]
__device__ __nv_bfloat16 d_Ght[8 * 4096 * 32];   // g^T:[b][m=4096][k=32]
__device__ __nv_bfloat16 d_Hh[8 * 128 * 1024];   // hh: [b][c=128][n=1024]
__device__ __nv_bfloat16 d_Ot[8 * 4096 * 128];   // o^T:[b][m=4096][c=128] (bf16)

__device__ __nv_bfloat16 d_Wc[192 * 256];        // BN-folded W for conv1|2|3 (oc-major)
__device__ float d_Bc[192];                      // folded biases conv1|2|3
__device__ __nv_bfloat16 d_W4h[256 * 128];       // BN-folded W4
__device__ float d_B4[256];                      // folded bias conv4

// ---------------- mma / ldmatrix / cp.async helpers -------------------------
__device__ __forceinline__ void mma_bf16(float c[4], unsigned a0, unsigned a1,
                                         unsigned a2, unsigned a3,
                                         unsigned b0, unsigned b1) {
    asm volatile(
        "mma.sync.aligned.m16n8k16.row.col.f32.bf16.bf16.f32 "
        "{%0,%1,%2,%3}, {%4,%5,%6,%7}, {%8,%9}, {%0,%1,%2,%3};"
        : "+f"(c[0]), "+f"(c[1]), "+f"(c[2]), "+f"(c[3])
        : "r"(a0), "r"(a1), "r"(a2), "r"(a3), "r"(b0), "r"(b1));
}
__device__ __forceinline__ unsigned smem_u32(const void* p) {
    return (unsigned)__cvta_generic_to_shared(p);
}
__device__ __forceinline__ void ldsm_x4(unsigned& r0, unsigned& r1, unsigned& r2,
                                        unsigned& r3, unsigned addr) {
    asm volatile("ldmatrix.sync.aligned.m8n8.x4.shared.b16 {%0,%1,%2,%3}, [%4];"
                 : "=r"(r0), "=r"(r1), "=r"(r2), "=r"(r3) : "r"(addr));
}
__device__ __forceinline__ void ldsm_x2t(unsigned& r0, unsigned& r1, unsigned addr) {
    asm volatile("ldmatrix.sync.aligned.m8n8.x2.trans.shared.b16 {%0,%1}, [%2];"
                 : "=r"(r0), "=r"(r1) : "r"(addr));
}
__device__ __forceinline__ unsigned bf2u(float a, float b) {
    __nv_bfloat162 h = __floats2bfloat162_rn(a, b);
    return *(unsigned*)&h;
}
__device__ __forceinline__ float ex2(float x) {
    float y;
    asm("ex2.approx.ftz.f32 %0, %1;" : "=f"(y) : "f"(x));
    return y;
}
__device__ __forceinline__ void cp16(void* dst, const void* src) {
    asm volatile("cp.async.ca.shared.global [%0], [%1], 16;\n"
                 :: "r"(smem_u32(dst)), "l"(src));
}
__device__ __forceinline__ void cp_commit() {
    asm volatile("cp.async.commit_group;\n" ::: "memory");
}
__device__ __forceinline__ void cp_wait0() {
    asm volatile("cp.async.wait_group 0;\n" ::: "memory");
}
__device__ __forceinline__ void cp_wait1() {
    asm volatile("cp.async.wait_group 1;\n" ::: "memory");
}

// ---------------------------------------------------------------------------
// prep v2: one (row, 16-col segment) per thread; single rsqrt per thread.
// ---------------------------------------------------------------------------
__global__ void __launch_bounds__(256) prep_kernel(
    const float* __restrict__ w1, const float* __restrict__ b1,
    const float* __restrict__ s1, const float* __restrict__ t1,
    const float* __restrict__ m1, const float* __restrict__ v1,
    const float* __restrict__ w2, const float* __restrict__ b2,
    const float* __restrict__ s2, const float* __restrict__ t2,
    const float* __restrict__ m2, const float* __restrict__ v2,
    const float* __restrict__ w3, const float* __restrict__ b3,
    const float* __restrict__ s3, const float* __restrict__ t3,
    const float* __restrict__ m3, const float* __restrict__ v3,
    const float* __restrict__ w4, const float* __restrict__ b4,
    const float* __restrict__ s4, const float* __restrict__ t4,
    const float* __restrict__ m4, const float* __restrict__ v4)
{
    int gid = blockIdx.x * 256 + threadIdx.x;

    if (gid < 3072) {
        int row = gid >> 4, seg = (gid & 15) * 16;
        const float* wsrc;
        float al;
        if (row < 32) {
            al = s1[row] * rsqrtf(v1[row] + EPSV);
            wsrc = w1 + row * 256;
        } else if (row < 64) {
            int o = row - 32;
            al = s2[o] * rsqrtf(v2[o] + EPSV);
            wsrc = w2 + o * 256;
        } else {
            int o = row - 64;
            al = s3[o] * rsqrtf(v3[o] + EPSV);
            wsrc = w3 + o * 256;
        }
        __nv_bfloat16 ov[16];
#pragma unroll
        for (int j = 0; j < 16; j++)
            ov[j] = __float2bfloat16_rn(wsrc[seg + j] * al);
        *(uint4*)(d_Wc + row * 256 + seg) = *(uint4*)&ov[0];
        *(uint4*)(d_Wc + row * 256 + seg + 8) = *(uint4*)&ov[8];
    } else if (gid < 5120) {
        int i2 = gid - 3072;
        int row = i2 >> 3, seg = (i2 & 7) * 16;
        float al = s4[row] * rsqrtf(v4[row] + EPSV);
        const float* wsrc = w4 + row * 128;
        __nv_bfloat16 ov[16];
#pragma unroll
        for (int j = 0; j < 16; j++)
            ov[j] = __float2bfloat16_rn(wsrc[seg + j] * al);
        *(uint4*)(d_W4h + row * 128 + seg) = *(uint4*)&ov[0];
        *(uint4*)(d_W4h + row * 128 + seg + 8) = *(uint4*)&ov[8];
    } else if (gid < 5568) {
        int oc = gid - 5120;
        if (oc < 192) {
            float al, bb;
            if (oc < 32) {
                al = s1[oc] * rsqrtf(v1[oc] + EPSV);
                bb = (b1[oc] - m1[oc]) * al + t1[oc];
            } else if (oc < 64) {
                int o = oc - 32;
                al = s2[o] * rsqrtf(v2[o] + EPSV);
                bb = (b2[o] - m2[o]) * al + t2[o];
            } else {
                int o = oc - 64;
                al = s3[o] * rsqrtf(v3[o] + EPSV);
                bb = (b3[o] - m3[o]) * al + t3[o];
            }
            d_Bc[oc] = bb;
        } else {
            int o = oc - 192;
            float al = s4[o] * rsqrtf(v4[o] + EPSV);
            d_B4[o] = (b4[o] - m4[o]) * al + t4[o];
        }
    }
}

// ---------------------------------------------------------------------------
// Fused conv1+2+3 via tensor cores. d_Fh output pre-scaled by log2(e).
// ---------------------------------------------------------------------------
__global__ void __launch_bounds__(512) conv123_kernel(const float* __restrict__ x)
{
    __shared__ __align__(16) char sm[45056];
    __nv_bfloat16* Xs = (__nv_bfloat16*)sm;             // [64][136]
    __nv_bfloat16* Ws = (__nv_bfloat16*)(sm + 17408);   // [192][72]
    __nv_bfloat16* HP1 = (__nv_bfloat16*)sm;            // [32][64]  (epilogue)
    __nv_bfloat16* HP3 = (__nv_bfloat16*)(sm + 4096);   // [128][64] (epilogue)
    __nv_bfloat16* Gt  = (__nv_bfloat16*)(sm + 20480);  // [128][40] (epilogue)

    const int b = blockIdx.y, r = blockIdx.x, t = threadIdx.x;
    const int lane = t & 31, wid = t >> 5;
    const int g = lane >> 2, t4 = lane & 3;
    const int oc0w = (wid & 3) * 48, m0w = (wid >> 2) * 32;

    const float* xb = x + (size_t)b * 1048576 + (size_t)r * 128;

    float c[3][4][4];
#pragma unroll
    for (int i = 0; i < 3; i++)
#pragma unroll
        for (int j = 0; j < 4; j++)
#pragma unroll
            for (int e = 0; e < 4; e++) c[i][j][e] = 0.f;

    for (int kc = 0; kc < 256; kc += 64) {
        __syncthreads();
#pragma unroll
        for (int j = 0; j < 4; j++) {
            int i = t + j * 512;
            int row = i >> 5, col4 = i & 31;
            float4 v = *(const float4*)(xb + (size_t)(kc + row) * 4096 + col4 * 4);
            uint2 u;
            u.x = bf2u(v.x, v.y);
            u.y = bf2u(v.z, v.w);
            *(uint2*)(Xs + row * 136 + col4 * 4) = u;
        }
#pragma unroll
        for (int j = 0; j < 3; j++) {
            int i = t + j * 512;
            int row = i >> 3, part = i & 7;
            *(uint4*)(Ws + row * 72 + part * 8) =
                *(const uint4*)(d_Wc + row * 256 + kc + part * 8);
        }
        __syncthreads();

#pragma unroll
        for (int ks = 0; ks < 4; ks++) {
            int k0 = ks * 16;
            unsigned a[3][4];
#pragma unroll
            for (int mt = 0; mt < 3; mt++) {
                unsigned addr = smem_u32(Ws + (oc0w + mt * 16 + (lane & 15)) * 72 +
                                         k0 + ((lane >> 4) << 3));
                ldsm_x4(a[mt][0], a[mt][1], a[mt][2], a[mt][3], addr);
            }
#pragma unroll
            for (int nt = 0; nt < 4; nt++) {
                unsigned b0, b1;
                unsigned addr = smem_u32(Xs + (k0 + (lane & 15)) * 136 + m0w + nt * 8);
                ldsm_x2t(b0, b1, addr);
#pragma unroll
                for (int mt = 0; mt < 3; mt++)
                    mma_bf16(c[mt][nt], a[mt][0], a[mt][1], a[mt][2], a[mt][3], b0, b1);
            }
        }
    }
    __syncthreads();

#pragma unroll
    for (int mt = 0; mt < 3; mt++) {
        int ocb = oc0w + mt * 16;
        float bg  = d_Bc[ocb + g];
        float bg8 = d_Bc[ocb + 8 + g];
#pragma unroll
        for (int nt = 0; nt < 4; nt++) {
            int mloc = m0w + nt * 8 + 2 * t4;
            int rh = mloc >> 6, cp = (mloc & 63) >> 1;
            float v0 = fmaxf(c[mt][nt][0] + bg, 0.f);
            float v1 = fmaxf(c[mt][nt][1] + bg, 0.f);
            float v2 = fmaxf(c[mt][nt][2] + bg8, 0.f);
            float v3 = fmaxf(c[mt][nt][3] + bg8, 0.f);
            if (ocb < 32) {
                HP1[(ocb + g) * 64 + rh * 32 + cp]     = __float2bfloat16_rn(fmaxf(v0, v1));
                HP1[(ocb + 8 + g) * 64 + rh * 32 + cp] = __float2bfloat16_rn(fmaxf(v2, v3));
            } else if (ocb < 64) {
                int oc = ocb - 32 + g;
                Gt[mloc * 40 + oc]           = __float2bfloat16_rn(v0);
                Gt[(mloc + 1) * 40 + oc]     = __float2bfloat16_rn(v1);
                Gt[mloc * 40 + oc + 8]       = __float2bfloat16_rn(v2);
                Gt[(mloc + 1) * 40 + oc + 8] = __float2bfloat16_rn(v3);
            } else {
                HP3[(ocb - 64 + g) * 64 + rh * 32 + cp]     = __float2bfloat16_rn(fmaxf(v0, v1));
                HP3[(ocb - 64 + 8 + g) * 64 + rh * 32 + cp] = __float2bfloat16_rn(fmaxf(v2, v3));
            }
        }
    }
    __syncthreads();

    {   // d_Fh: 32 n x 32 oc, scaled by log2(e) for base-2 softmax
        int cp = t >> 4, oc0 = (t & 15) * 2;
        float f0 = __bfloat162float(__hmax(HP1[oc0 * 64 + cp], HP1[oc0 * 64 + 32 + cp]));
        float f1 = __bfloat162float(__hmax(HP1[(oc0 + 1) * 64 + cp], HP1[(oc0 + 1) * 64 + 32 + cp]));
        __nv_bfloat162 h = __floats2bfloat162_rn(f0 * LOG2E, f1 * LOG2E);
        *(__nv_bfloat162*)(d_Fh + (size_t)b * 32768 + (size_t)(r * 32 + cp) * 32 + oc0) = h;
    }
    {   // d_Hh: 128 c x 32 n
        int cc = t >> 2, q = (t & 3) * 8;
        __nv_bfloat16 out8[8];
#pragma unroll
        for (int jj = 0; jj < 8; jj++)
            out8[jj] = __hmax(HP3[cc * 64 + q + jj], HP3[cc * 64 + 32 + q + jj]);
        *(uint4*)(d_Hh + (size_t)b * 131072 + (size_t)cc * 1024 + r * 32 + q) =
            *(uint4*)out8;
    }
    {   // d_Ght: 128 m x 32 k
        int row = t >> 2, part = t & 3;
        *(uint4*)(d_Ght + (size_t)b * 131072 + (size_t)(r * 128 + row) * 32 + part * 8) =
            *(uint4*)(Gt + row * 40 + part * 8);
    }
}

// ---------------------------------------------------------------------------
// Flash attention v3 + cp.async double-buffered staging; base-2 softmax (ex2).
// Dynamic smem: Gs [0,10240), buf0 {Fs,Vs} [10240,33792), buf1 [33792,57344).
// ---------------------------------------------------------------------------
__device__ __forceinline__ void stage_attn_chunk(
    __nv_bfloat16* Fs, __nv_bfloat16* Vs,
    const __nv_bfloat16* fB, const __nv_bfloat16* hB, int n0, int t)
{
    {
        int row = t >> 2, part = t & 3;
        cp16(Fs + row * 40 + part * 8, fB + (size_t)(n0 + row) * 32 + part * 8);
    }
    {
        int cpos = t >> 1, nq = (t & 1) * 32;
        const __nv_bfloat16* src = hB + (size_t)cpos * 1024 + n0 + nq;
#pragma unroll
        for (int j = 0; j < 4; j++)
            cp16(Vs + cpos * 72 + nq + j * 8, src + j * 8);
    }
}

__global__ void __launch_bounds__(256, 2) attn_kernel()
{
    extern __shared__ __align__(16) char smd[];
    __nv_bfloat16* Gs  = (__nv_bfloat16*)smd;
    __nv_bfloat16* Fsb[2] = { (__nv_bfloat16*)(smd + 10240),
                              (__nv_bfloat16*)(smd + 33792) };
    __nv_bfloat16* Vsb[2] = { (__nv_bfloat16*)(smd + 15360),
                              (__nv_bfloat16*)(smd + 38912) };

    const int b = blockIdx.y;
    const int m0 = blockIdx.x * 128;
    const int t = threadIdx.x;
    const int lane = t & 31, wid = t >> 5;
    const int g = lane >> 2, t4 = lane & 3;
    const int q = lane & 7, sel = lane >> 3;

    const __nv_bfloat16* gB = d_Ght + (size_t)b * 131072;
    const __nv_bfloat16* fB = d_Fh + (size_t)b * 32768;
    const __nv_bfloat16* hB = d_Hh + (size_t)b * 131072;

    stage_attn_chunk(Fsb[0], Vsb[0], fB, hB, 0, t);
    cp_commit();

#pragma unroll
    for (int j = 0; j < 2; j++) {
        int i = t + j * 256;
        int row = i >> 2, part = i & 3;
        *(uint4*)&Gs[row * 40 + part * 8] =
            *(const uint4*)(gB + (size_t)(m0 + row) * 32 + part * 8);
    }
    __syncthreads();

    unsigned ag[2][4];
#pragma unroll
    for (int kt = 0; kt < 2; kt++) {
        unsigned addr = smem_u32(Gs + (wid * 16 + (lane & 15)) * 40 +
                                 kt * 16 + ((lane >> 4) << 3));
        ldsm_x4(ag[kt][0], ag[kt][1], ag[kt][2], ag[kt][3], addr);
    }

    float o[16][4];
#pragma unroll
    for (int i = 0; i < 16; i++)
#pragma unroll
        for (int e = 0; e < 4; e++) o[i][e] = 0.f;
    float rm0 = -1e30f, rm1 = -1e30f, rs0 = 0.f, rs1 = 0.f;

    for (int it = 0; it < 16; it++) {
        const int cur = it & 1;
        if (it < 15) {
            stage_attn_chunk(Fsb[cur ^ 1], Vsb[cur ^ 1], fB, hB, (it + 1) * 64, t);
            cp_commit();
            cp_wait1();
        } else {
            cp_wait0();
        }
        __syncthreads();

        const __nv_bfloat16* Fs = Fsb[cur];
        const __nv_bfloat16* Vs = Vsb[cur];

        // ---- GEMM1: S2[16m][64n] per warp (base-2 scaled scores) ----
        float sc[8][4];
#pragma unroll
        for (int nt = 0; nt < 8; nt++)
#pragma unroll
            for (int e = 0; e < 4; e++) sc[nt][e] = 0.f;
#pragma unroll
        for (int kt = 0; kt < 2; kt++)
#pragma unroll
            for (int ntp = 0; ntp < 4; ntp++) {
                unsigned b00, b01, b10, b11;
                unsigned addr = smem_u32(Fs + (ntp * 16 + (sel >> 1) * 8 + q) * 40 +
                                         kt * 16 + (sel & 1) * 8);
                ldsm_x4(b00, b01, b10, b11, addr);
                mma_bf16(sc[ntp * 2],     ag[kt][0], ag[kt][1], ag[kt][2], ag[kt][3], b00, b01);
                mma_bf16(sc[ntp * 2 + 1], ag[kt][0], ag[kt][1], ag[kt][2], ag[kt][3], b10, b11);
            }

        // ---- in-register online softmax (base 2; rows g, g+8) ----
        float cm0 = -1e30f, cm1 = -1e30f;
#pragma unroll
        for (int nt = 0; nt < 8; nt++) {
            cm0 = fmaxf(cm0, fmaxf(sc[nt][0], sc[nt][1]));
            cm1 = fmaxf(cm1, fmaxf(sc[nt][2], sc[nt][3]));
        }
        cm0 = fmaxf(cm0, __shfl_xor_sync(0xffffffffu, cm0, 1));
        cm0 = fmaxf(cm0, __shfl_xor_sync(0xffffffffu, cm0, 2));
        cm1 = fmaxf(cm1, __shfl_xor_sync(0xffffffffu, cm1, 1));
        cm1 = fmaxf(cm1, __shfl_xor_sync(0xffffffffu, cm1, 2));
        float nm0 = fmaxf(rm0, cm0), nm1 = fmaxf(rm1, cm1);
        float scl0 = ex2(rm0 - nm0), scl1 = ex2(rm1 - nm1);
        rm0 = nm0; rm1 = nm1;
        rs0 *= scl0; rs1 *= scl1;

        unsigned pa[4][4];
        float s0a = 0.f, s1a = 0.f;
#pragma unroll
        for (int kt2 = 0; kt2 < 4; kt2++) {
            float e00 = ex2(sc[2 * kt2][0] - nm0);
            float e01 = ex2(sc[2 * kt2][1] - nm0);
            float e02 = ex2(sc[2 * kt2][2] - nm1);
            float e03 = ex2(sc[2 * kt2][3] - nm1);
            float e10 = ex2(sc[2 * kt2 + 1][0] - nm0);
            float e11 = ex2(sc[2 * kt2 + 1][1] - nm0);
            float e12 = ex2(sc[2 * kt2 + 1][2] - nm1);
            float e13 = ex2(sc[2 * kt2 + 1][3] - nm1);
            pa[kt2][0] = bf2u(e00, e01);
            pa[kt2][1] = bf2u(e02, e03);
            pa[kt2][2] = bf2u(e10, e11);
            pa[kt2][3] = bf2u(e12, e13);
            s0a += e00 + e01 + e10 + e11;
            s1a += e02 + e03 + e12 + e13;
        }
        rs0 += s0a; rs1 += s1a;

#pragma unroll
        for (int ct = 0; ct < 16; ct++) {
            o[ct][0] *= scl0; o[ct][1] *= scl0;
            o[ct][2] *= scl1; o[ct][3] *= scl1;
        }

        // ---- GEMM2: O[16m][128c] += P . V^T ----
#pragma unroll
        for (int kt2 = 0; kt2 < 4; kt2++)
#pragma unroll
            for (int cg2 = 0; cg2 < 8; cg2++) {
                unsigned b00, b01, b10, b11;
                unsigned addr = smem_u32(Vs + (cg2 * 16 + (sel >> 1) * 8 + q) * 72 +
                                         kt2 * 16 + (sel & 1) * 8);
                ldsm_x4(b00, b01, b10, b11, addr);
                mma_bf16(o[cg2 * 2],     pa[kt2][0], pa[kt2][1], pa[kt2][2], pa[kt2][3], b00, b01);
                mma_bf16(o[cg2 * 2 + 1], pa[kt2][0], pa[kt2][1], pa[kt2][2], pa[kt2][3], b10, b11);
            }
        __syncthreads();
    }

    // ---- normalize + store bf16 O[m][c] ----
    rs0 += __shfl_xor_sync(0xffffffffu, rs0, 1);
    rs0 += __shfl_xor_sync(0xffffffffu, rs0, 2);
    rs1 += __shfl_xor_sync(0xffffffffu, rs1, 1);
    rs1 += __shfl_xor_sync(0xffffffffu, rs1, 2);
    float inv0 = 1.f / rs0, inv1 = 1.f / rs1;

    __nv_bfloat16* oB = d_Ot + (size_t)b * 524288;
    int row0 = m0 + wid * 16 + g;
#pragma unroll
    for (int ct = 0; ct < 16; ct++) {
        int cc = ct * 8 + 2 * t4;
        *(__nv_bfloat162*)(oB + (size_t)row0 * 128 + cc) =
            __floats2bfloat162_rn(o[ct][0] * inv0, o[ct][1] * inv0);
        *(__nv_bfloat162*)(oB + (size_t)(row0 + 8) * 128 + cc) =
            __floats2bfloat162_rn(o[ct][2] * inv1, o[ct][3] * inv1);
    }
}

// ---------------------------------------------------------------------------
// conv4 (R12 configuration): C[128 oc][128 m] per block, K=128,
// both K-chunks prefetched in separate cp.async groups (wait1/wait0 pipeline).
// Dynamic smem: buf0 {Ots,W4s} [0,36864), buf1 [36864,73728).
// ---------------------------------------------------------------------------
__global__ void __launch_bounds__(256) conv4_kernel(
    const float* __restrict__ x, const float* __restrict__ gamma,
    float* __restrict__ out)
{
    extern __shared__ __align__(16) char smd[];
    __nv_bfloat16* Otb[2] = { (__nv_bfloat16*)smd,
                              (__nv_bfloat16*)(smd + 36864) };
    __nv_bfloat16* W4b[2] = { (__nv_bfloat16*)(smd + 18432),
                              (__nv_bfloat16*)(smd + 55296) };

    const int b = blockIdx.z, OC0 = blockIdx.y * 128, pos0 = blockIdx.x * 128;
    const int t = threadIdx.x;
    const int lane = t & 31, wid = t >> 5;
    const int g = lane >> 2, t4 = lane & 3;
    const int q = lane & 7, sel = lane >> 3;
    const int oc0w = (wid & 3) * 32, m0w = (wid >> 2) * 64;

    const __nv_bfloat16* oB = d_Ot + ((size_t)b * 4096 + pos0) * 128;

    // prefetch both K-chunks in separate groups
#pragma unroll
    for (int kh = 0; kh < 2; kh++) {
        int row = t >> 1, cq = (t & 1) * 32;
        const __nv_bfloat16* osrc = oB + (size_t)row * 128 + kh * 64 + cq;
        const __nv_bfloat16* wsrc = d_W4h + (size_t)(OC0 + row) * 128 + kh * 64 + cq;
#pragma unroll
        for (int j = 0; j < 4; j++) {
            cp16(Otb[kh] + row * 72 + cq + j * 8, osrc + j * 8);
            cp16(W4b[kh] + row * 72 + cq + j * 8, wsrc + j * 8);
        }
        cp_commit();
    }

    float c[2][8][4];
#pragma unroll
    for (int i = 0; i < 2; i++)
#pragma unroll
        for (int j = 0; j < 8; j++)
#pragma unroll
            for (int e = 0; e < 4; e++) c[i][j][e] = 0.f;

#pragma unroll
    for (int kh = 0; kh < 2; kh++) {
        if (kh == 0) cp_wait1(); else cp_wait0();
        __syncthreads();
        const __nv_bfloat16* Ots = Otb[kh];
        const __nv_bfloat16* W4s = W4b[kh];

#pragma unroll
        for (int ks = 0; ks < 4; ks++) {
            int k0 = ks * 16;
            unsigned a[2][4];
#pragma unroll
            for (int mt = 0; mt < 2; mt++) {
                unsigned addr = smem_u32(W4s + (oc0w + mt * 16 + (lane & 15)) * 72 +
                                         k0 + ((lane >> 4) << 3));
                ldsm_x4(a[mt][0], a[mt][1], a[mt][2], a[mt][3], addr);
            }
#pragma unroll
            for (int mgp = 0; mgp < 4; mgp++) {
                unsigned b00, b01, b10, b11;
                unsigned addr = smem_u32(Ots + (m0w + mgp * 16 + (sel >> 1) * 8 + q) * 72 +
                                         k0 + (sel & 1) * 8);
                ldsm_x4(b00, b01, b10, b11, addr);
                mma_bf16(c[0][mgp * 2],     a[0][0], a[0][1], a[0][2], a[0][3], b00, b01);
                mma_bf16(c[0][mgp * 2 + 1], a[0][0], a[0][1], a[0][2], a[0][3], b10, b11);
                mma_bf16(c[1][mgp * 2],     a[1][0], a[1][1], a[1][2], a[1][3], b00, b01);
                mma_bf16(c[1][mgp * 2 + 1], a[1][0], a[1][1], a[1][2], a[1][3], b10, b11);
            }
        }
    }

    float gm = *gamma;
#pragma unroll
    for (int mt = 0; mt < 2; mt++) {
        int ocA = OC0 + oc0w + mt * 16 + g;
        int ocB = ocA + 8;
        float bA = d_B4[ocA], bB = d_B4[ocB];
        size_t baseA = (size_t)b * 1048576 + (size_t)ocA * 4096 + pos0 + m0w;
        size_t baseB = (size_t)b * 1048576 + (size_t)ocB * 4096 + pos0 + m0w;
#pragma unroll
        for (int nt = 0; nt < 8; nt++) {
            int moff = nt * 8 + 2 * t4;
            float2 xa = *(const float2*)(x + baseA + moff);
            float2 ra;
            ra.x = gm * (c[mt][nt][0] + bA) + xa.x;
            ra.y = gm * (c[mt][nt][1] + bA) + xa.y;
            *(float2*)(out + baseA + moff) = ra;
            float2 xb = *(const float2*)(x + baseB + moff);
            float2 rb;
            rb.x = gm * (c[mt][nt][2] + bB) + xb.x;
            rb.y = gm * (c[mt][nt][3] + bB) + xb.y;
            *(float2*)(out + baseB + moff) = rb;
        }
    }
}

// ---------------------------------------------------------------------------
extern "C" void kernel_launch(void* const* d_in, const int* in_sizes, int n_in,
                              void* d_out, int out_size)
{
    const float* x = (const float*)d_in[0];
    const float* w1 = (const float*)d_in[1];
    const float* b1 = (const float*)d_in[2];
    const float* s1 = (const float*)d_in[3];
    const float* t1 = (const float*)d_in[4];
    const float* m1 = (const float*)d_in[5];
    const float* v1 = (const float*)d_in[6];
    const float* w2 = (const float*)d_in[7];
    const float* b2 = (const float*)d_in[8];
    const float* s2 = (const float*)d_in[9];
    const float* t2 = (const float*)d_in[10];
    const float* m2 = (const float*)d_in[11];
    const float* v2 = (const float*)d_in[12];
    const float* w3 = (const float*)d_in[13];
    const float* b3 = (const float*)d_in[14];
    const float* s3 = (const float*)d_in[15];
    const float* t3 = (const float*)d_in[16];
    const float* m3 = (const float*)d_in[17];
    const float* v3 = (const float*)d_in[18];
    const float* w4 = (const float*)d_in[19];
    const float* b4 = (const float*)d_in[20];
    const float* s4 = (const float*)d_in[21];
    const float* t4 = (const float*)d_in[22];
    const float* m4 = (const float*)d_in[23];
    const float* v4 = (const float*)d_in[24];
    const float* gamma = (const float*)d_in[25];

    cudaFuncSetAttribute(attn_kernel,
                         cudaFuncAttributeMaxDynamicSharedMemorySize, 57344);
    cudaFuncSetAttribute(conv4_kernel,
                         cudaFuncAttributeMaxDynamicSharedMemorySize, 73728);

    prep_kernel<<<22, 256>>>(w1, b1, s1, t1, m1, v1,
                             w2, b2, s2, t2, m2, v2,
                             w3, b3, s3, t3, m3, v3,
                             w4, b4, s4, t4, m4, v4);
    conv123_kernel<<<dim3(32, 8), 512>>>(x);
    attn_kernel<<<dim3(32, 8), 256, 57344>>>();
    conv4_kernel<<<dim3(32, 2, 8), 256, 73728>>>(x, gamma, (float*)d_out);
}

// round 17
// speedup vs baseline: 1.1105x; 1.0216x over previous
#include <cuda_runtime.h>
#include <cuda_bf16.h>

#define EPSV 1e-5f
#define LOG2E 1.4426950408889634f

// ---------------- scratch (device globals; no cudaMalloc allowed) ----------
__device__ __nv_bfloat16 d_Fh[8 * 1024 * 32];    // f*log2e: [b][n=1024][k=32]
__device__ __nv_bfloat16 d_Ght[8 * 4096 * 32];   // g^T:[b][m=4096][k=32]
__device__ __nv_bfloat16 d_Hh[8 * 128 * 1024];   // hh: [b][c=128][n=1024]
__device__ __nv_bfloat16 d_Ot[8 * 4096 * 128];   // o^T:[b][m=4096][c=128] (bf16)

__device__ __nv_bfloat16 d_Wc[192 * 256];        // BN-folded W for conv1|2|3 (oc-major)
__device__ float d_Bc[192];                      // folded biases conv1|2|3
__device__ __nv_bfloat16 d_W4h[256 * 128];       // BN-folded W4
__device__ float d_B4[256];                      // folded bias conv4

// ---------------- mma / ldmatrix / cp.async helpers -------------------------
__device__ __forceinline__ void mma_bf16(float c[4], unsigned a0, unsigned a1,
                                         unsigned a2, unsigned a3,
                                         unsigned b0, unsigned b1) {
    asm volatile(
        "mma.sync.aligned.m16n8k16.row.col.f32.bf16.bf16.f32 "
        "{%0,%1,%2,%3}, {%4,%5,%6,%7}, {%8,%9}, {%0,%1,%2,%3};"
        : "+f"(c[0]), "+f"(c[1]), "+f"(c[2]), "+f"(c[3])
        : "r"(a0), "r"(a1), "r"(a2), "r"(a3), "r"(b0), "r"(b1));
}
__device__ __forceinline__ unsigned smem_u32(const void* p) {
    return (unsigned)__cvta_generic_to_shared(p);
}
__device__ __forceinline__ void ldsm_x4(unsigned& r0, unsigned& r1, unsigned& r2,
                                        unsigned& r3, unsigned addr) {
    asm volatile("ldmatrix.sync.aligned.m8n8.x4.shared.b16 {%0,%1,%2,%3}, [%4];"
                 : "=r"(r0), "=r"(r1), "=r"(r2), "=r"(r3) : "r"(addr));
}
__device__ __forceinline__ void ldsm_x2t(unsigned& r0, unsigned& r1, unsigned addr) {
    asm volatile("ldmatrix.sync.aligned.m8n8.x2.trans.shared.b16 {%0,%1}, [%2];"
                 : "=r"(r0), "=r"(r1) : "r"(addr));
}
__device__ __forceinline__ unsigned bf2u(float a, float b) {
    __nv_bfloat162 h = __floats2bfloat162_rn(a, b);
    return *(unsigned*)&h;
}
__device__ __forceinline__ float ex2(float x) {
    float y;
    asm("ex2.approx.ftz.f32 %0, %1;" : "=f"(y) : "f"(x));
    return y;
}
__device__ __forceinline__ void cp16(void* dst, const void* src) {
    asm volatile("cp.async.ca.shared.global [%0], [%1], 16;\n"
                 :: "r"(smem_u32(dst)), "l"(src));
}
__device__ __forceinline__ void cp_commit() {
    asm volatile("cp.async.commit_group;\n" ::: "memory");
}
__device__ __forceinline__ void cp_wait0() {
    asm volatile("cp.async.wait_group 0;\n" ::: "memory");
}
__device__ __forceinline__ void cp_wait1() {
    asm volatile("cp.async.wait_group 1;\n" ::: "memory");
}

// ---------------------------------------------------------------------------
// prep v2: one (row, 16-col segment) per thread; single rsqrt per thread.
// ---------------------------------------------------------------------------
__global__ void __launch_bounds__(256) prep_kernel(
    const float* __restrict__ w1, const float* __restrict__ b1,
    const float* __restrict__ s1, const float* __restrict__ t1,
    const float* __restrict__ m1, const float* __restrict__ v1,
    const float* __restrict__ w2, const float* __restrict__ b2,
    const float* __restrict__ s2, const float* __restrict__ t2,
    const float* __restrict__ m2, const float* __restrict__ v2,
    const float* __restrict__ w3, const float* __restrict__ b3,
    const float* __restrict__ s3, const float* __restrict__ t3,
    const float* __restrict__ m3, const float* __restrict__ v3,
    const float* __restrict__ w4, const float* __restrict__ b4,
    const float* __restrict__ s4, const float* __restrict__ t4,
    const float* __restrict__ m4, const float* __restrict__ v4)
{
    int gid = blockIdx.x * 256 + threadIdx.x;

    if (gid < 3072) {
        int row = gid >> 4, seg = (gid & 15) * 16;
        const float* wsrc;
        float al;
        if (row < 32) {
            al = s1[row] * rsqrtf(v1[row] + EPSV);
            wsrc = w1 + row * 256;
        } else if (row < 64) {
            int o = row - 32;
            al = s2[o] * rsqrtf(v2[o] + EPSV);
            wsrc = w2 + o * 256;
        } else {
            int o = row - 64;
            al = s3[o] * rsqrtf(v3[o] + EPSV);
            wsrc = w3 + o * 256;
        }
        __nv_bfloat16 ov[16];
#pragma unroll
        for (int j = 0; j < 16; j++)
            ov[j] = __float2bfloat16_rn(wsrc[seg + j] * al);
        *(uint4*)(d_Wc + row * 256 + seg) = *(uint4*)&ov[0];
        *(uint4*)(d_Wc + row * 256 + seg + 8) = *(uint4*)&ov[8];
    } else if (gid < 5120) {
        int i2 = gid - 3072;
        int row = i2 >> 3, seg = (i2 & 7) * 16;
        float al = s4[row] * rsqrtf(v4[row] + EPSV);
        const float* wsrc = w4 + row * 128;
        __nv_bfloat16 ov[16];
#pragma unroll
        for (int j = 0; j < 16; j++)
            ov[j] = __float2bfloat16_rn(wsrc[seg + j] * al);
        *(uint4*)(d_W4h + row * 128 + seg) = *(uint4*)&ov[0];
        *(uint4*)(d_W4h + row * 128 + seg + 8) = *(uint4*)&ov[8];
    } else if (gid < 5568) {
        int oc = gid - 5120;
        if (oc < 192) {
            float al, bb;
            if (oc < 32) {
                al = s1[oc] * rsqrtf(v1[oc] + EPSV);
                bb = (b1[oc] - m1[oc]) * al + t1[oc];
            } else if (oc < 64) {
                int o = oc - 32;
                al = s2[o] * rsqrtf(v2[o] + EPSV);
                bb = (b2[o] - m2[o]) * al + t2[o];
            } else {
                int o = oc - 64;
                al = s3[o] * rsqrtf(v3[o] + EPSV);
                bb = (b3[o] - m3[o]) * al + t3[o];
            }
            d_Bc[oc] = bb;
        } else {
            int o = oc - 192;
            float al = s4[o] * rsqrtf(v4[o] + EPSV);
            d_B4[o] = (b4[o] - m4[o]) * al + t4[o];
        }
    }
}

// ---------------------------------------------------------------------------
// Fused conv1+2+3 via tensor cores. d_Fh output pre-scaled by log2(e).
// ---------------------------------------------------------------------------
__global__ void __launch_bounds__(512) conv123_kernel(const float* __restrict__ x)
{
    __shared__ __align__(16) char sm[45056];
    __nv_bfloat16* Xs = (__nv_bfloat16*)sm;             // [64][136]
    __nv_bfloat16* Ws = (__nv_bfloat16*)(sm + 17408);   // [192][72]
    __nv_bfloat16* HP1 = (__nv_bfloat16*)sm;            // [32][64]  (epilogue)
    __nv_bfloat16* HP3 = (__nv_bfloat16*)(sm + 4096);   // [128][64] (epilogue)
    __nv_bfloat16* Gt  = (__nv_bfloat16*)(sm + 20480);  // [128][40] (epilogue)

    const int b = blockIdx.y, r = blockIdx.x, t = threadIdx.x;
    const int lane = t & 31, wid = t >> 5;
    const int g = lane >> 2, t4 = lane & 3;
    const int oc0w = (wid & 3) * 48, m0w = (wid >> 2) * 32;

    const float* xb = x + (size_t)b * 1048576 + (size_t)r * 128;

    float c[3][4][4];
#pragma unroll
    for (int i = 0; i < 3; i++)
#pragma unroll
        for (int j = 0; j < 4; j++)
#pragma unroll
            for (int e = 0; e < 4; e++) c[i][j][e] = 0.f;

    for (int kc = 0; kc < 256; kc += 64) {
        __syncthreads();
#pragma unroll
        for (int j = 0; j < 4; j++) {
            int i = t + j * 512;
            int row = i >> 5, col4 = i & 31;
            float4 v = *(const float4*)(xb + (size_t)(kc + row) * 4096 + col4 * 4);
            uint2 u;
            u.x = bf2u(v.x, v.y);
            u.y = bf2u(v.z, v.w);
            *(uint2*)(Xs + row * 136 + col4 * 4) = u;
        }
#pragma unroll
        for (int j = 0; j < 3; j++) {
            int i = t + j * 512;
            int row = i >> 3, part = i & 7;
            *(uint4*)(Ws + row * 72 + part * 8) =
                *(const uint4*)(d_Wc + row * 256 + kc + part * 8);
        }
        __syncthreads();

#pragma unroll
        for (int ks = 0; ks < 4; ks++) {
            int k0 = ks * 16;
            unsigned a[3][4];
#pragma unroll
            for (int mt = 0; mt < 3; mt++) {
                unsigned addr = smem_u32(Ws + (oc0w + mt * 16 + (lane & 15)) * 72 +
                                         k0 + ((lane >> 4) << 3));
                ldsm_x4(a[mt][0], a[mt][1], a[mt][2], a[mt][3], addr);
            }
#pragma unroll
            for (int nt = 0; nt < 4; nt++) {
                unsigned b0, b1;
                unsigned addr = smem_u32(Xs + (k0 + (lane & 15)) * 136 + m0w + nt * 8);
                ldsm_x2t(b0, b1, addr);
#pragma unroll
                for (int mt = 0; mt < 3; mt++)
                    mma_bf16(c[mt][nt], a[mt][0], a[mt][1], a[mt][2], a[mt][3], b0, b1);
            }
        }
    }
    __syncthreads();

#pragma unroll
    for (int mt = 0; mt < 3; mt++) {
        int ocb = oc0w + mt * 16;
        float bg  = d_Bc[ocb + g];
        float bg8 = d_Bc[ocb + 8 + g];
#pragma unroll
        for (int nt = 0; nt < 4; nt++) {
            int mloc = m0w + nt * 8 + 2 * t4;
            int rh = mloc >> 6, cp = (mloc & 63) >> 1;
            float v0 = fmaxf(c[mt][nt][0] + bg, 0.f);
            float v1 = fmaxf(c[mt][nt][1] + bg, 0.f);
            float v2 = fmaxf(c[mt][nt][2] + bg8, 0.f);
            float v3 = fmaxf(c[mt][nt][3] + bg8, 0.f);
            if (ocb < 32) {
                HP1[(ocb + g) * 64 + rh * 32 + cp]     = __float2bfloat16_rn(fmaxf(v0, v1));
                HP1[(ocb + 8 + g) * 64 + rh * 32 + cp] = __float2bfloat16_rn(fmaxf(v2, v3));
            } else if (ocb < 64) {
                int oc = ocb - 32 + g;
                Gt[mloc * 40 + oc]           = __float2bfloat16_rn(v0);
                Gt[(mloc + 1) * 40 + oc]     = __float2bfloat16_rn(v1);
                Gt[mloc * 40 + oc + 8]       = __float2bfloat16_rn(v2);
                Gt[(mloc + 1) * 40 + oc + 8] = __float2bfloat16_rn(v3);
            } else {
                HP3[(ocb - 64 + g) * 64 + rh * 32 + cp]     = __float2bfloat16_rn(fmaxf(v0, v1));
                HP3[(ocb - 64 + 8 + g) * 64 + rh * 32 + cp] = __float2bfloat16_rn(fmaxf(v2, v3));
            }
        }
    }
    __syncthreads();

    {   // d_Fh: 32 n x 32 oc, scaled by log2(e) for base-2 softmax
        int cp = t >> 4, oc0 = (t & 15) * 2;
        float f0 = __bfloat162float(__hmax(HP1[oc0 * 64 + cp], HP1[oc0 * 64 + 32 + cp]));
        float f1 = __bfloat162float(__hmax(HP1[(oc0 + 1) * 64 + cp], HP1[(oc0 + 1) * 64 + 32 + cp]));
        __nv_bfloat162 h = __floats2bfloat162_rn(f0 * LOG2E, f1 * LOG2E);
        *(__nv_bfloat162*)(d_Fh + (size_t)b * 32768 + (size_t)(r * 32 + cp) * 32 + oc0) = h;
    }
    {   // d_Hh: 128 c x 32 n
        int cc = t >> 2, q = (t & 3) * 8;
        __nv_bfloat16 out8[8];
#pragma unroll
        for (int jj = 0; jj < 8; jj++)
            out8[jj] = __hmax(HP3[cc * 64 + q + jj], HP3[cc * 64 + 32 + q + jj]);
        *(uint4*)(d_Hh + (size_t)b * 131072 + (size_t)cc * 1024 + r * 32 + q) =
            *(uint4*)out8;
    }
    {   // d_Ght: 128 m x 32 k
        int row = t >> 2, part = t & 3;
        *(uint4*)(d_Ght + (size_t)b * 131072 + (size_t)(r * 128 + row) * 32 + part * 8) =
            *(uint4*)(Gt + row * 40 + part * 8);
    }
}

// ---------------------------------------------------------------------------
// Flash attention v3 + cp.async double-buffered staging; base-2 softmax (ex2).
// Dynamic smem: Gs [0,10240), buf0 {Fs,Vs} [10240,33792), buf1 [33792,57344).
// ---------------------------------------------------------------------------
__device__ __forceinline__ void stage_attn_chunk(
    __nv_bfloat16* Fs, __nv_bfloat16* Vs,
    const __nv_bfloat16* fB, const __nv_bfloat16* hB, int n0, int t)
{
    {
        int row = t >> 2, part = t & 3;
        cp16(Fs + row * 40 + part * 8, fB + (size_t)(n0 + row) * 32 + part * 8);
    }
    {
        int cpos = t >> 1, nq = (t & 1) * 32;
        const __nv_bfloat16* src = hB + (size_t)cpos * 1024 + n0 + nq;
#pragma unroll
        for (int j = 0; j < 4; j++)
            cp16(Vs + cpos * 72 + nq + j * 8, src + j * 8);
    }
}

__global__ void __launch_bounds__(256, 2) attn_kernel()
{
    extern __shared__ __align__(16) char smd[];
    __nv_bfloat16* Gs  = (__nv_bfloat16*)smd;
    __nv_bfloat16* Fsb[2] = { (__nv_bfloat16*)(smd + 10240),
                              (__nv_bfloat16*)(smd + 33792) };
    __nv_bfloat16* Vsb[2] = { (__nv_bfloat16*)(smd + 15360),
                              (__nv_bfloat16*)(smd + 38912) };

    const int b = blockIdx.y;
    const int m0 = blockIdx.x * 128;
    const int t = threadIdx.x;
    const int lane = t & 31, wid = t >> 5;
    const int g = lane >> 2, t4 = lane & 3;
    const int q = lane & 7, sel = lane >> 3;

    const __nv_bfloat16* gB = d_Ght + (size_t)b * 131072;
    const __nv_bfloat16* fB = d_Fh + (size_t)b * 32768;
    const __nv_bfloat16* hB = d_Hh + (size_t)b * 131072;

    stage_attn_chunk(Fsb[0], Vsb[0], fB, hB, 0, t);
    cp_commit();

#pragma unroll
    for (int j = 0; j < 2; j++) {
        int i = t + j * 256;
        int row = i >> 2, part = i & 3;
        *(uint4*)&Gs[row * 40 + part * 8] =
            *(const uint4*)(gB + (size_t)(m0 + row) * 32 + part * 8);
    }
    __syncthreads();

    unsigned ag[2][4];
#pragma unroll
    for (int kt = 0; kt < 2; kt++) {
        unsigned addr = smem_u32(Gs + (wid * 16 + (lane & 15)) * 40 +
                                 kt * 16 + ((lane >> 4) << 3));
        ldsm_x4(ag[kt][0], ag[kt][1], ag[kt][2], ag[kt][3], addr);
    }

    float o[16][4];
#pragma unroll
    for (int i = 0; i < 16; i++)
#pragma unroll
        for (int e = 0; e < 4; e++) o[i][e] = 0.f;
    float rm0 = -1e30f, rm1 = -1e30f, rs0 = 0.f, rs1 = 0.f;

    for (int it = 0; it < 16; it++) {
        const int cur = it & 1;
        if (it < 15) {
            stage_attn_chunk(Fsb[cur ^ 1], Vsb[cur ^ 1], fB, hB, (it + 1) * 64, t);
            cp_commit();
            cp_wait1();
        } else {
            cp_wait0();
        }
        __syncthreads();

        const __nv_bfloat16* Fs = Fsb[cur];
        const __nv_bfloat16* Vs = Vsb[cur];

        // ---- GEMM1: S2[16m][64n] per warp (base-2 scaled scores) ----
        float sc[8][4];
#pragma unroll
        for (int nt = 0; nt < 8; nt++)
#pragma unroll
            for (int e = 0; e < 4; e++) sc[nt][e] = 0.f;
#pragma unroll
        for (int kt = 0; kt < 2; kt++)
#pragma unroll
            for (int ntp = 0; ntp < 4; ntp++) {
                unsigned b00, b01, b10, b11;
                unsigned addr = smem_u32(Fs + (ntp * 16 + (sel >> 1) * 8 + q) * 40 +
                                         kt * 16 + (sel & 1) * 8);
                ldsm_x4(b00, b01, b10, b11, addr);
                mma_bf16(sc[ntp * 2],     ag[kt][0], ag[kt][1], ag[kt][2], ag[kt][3], b00, b01);
                mma_bf16(sc[ntp * 2 + 1], ag[kt][0], ag[kt][1], ag[kt][2], ag[kt][3], b10, b11);
            }

        // ---- in-register online softmax (base 2; rows g, g+8) ----
        float cm0 = -1e30f, cm1 = -1e30f;
#pragma unroll
        for (int nt = 0; nt < 8; nt++) {
            cm0 = fmaxf(cm0, fmaxf(sc[nt][0], sc[nt][1]));
            cm1 = fmaxf(cm1, fmaxf(sc[nt][2], sc[nt][3]));
        }
        cm0 = fmaxf(cm0, __shfl_xor_sync(0xffffffffu, cm0, 1));
        cm0 = fmaxf(cm0, __shfl_xor_sync(0xffffffffu, cm0, 2));
        cm1 = fmaxf(cm1, __shfl_xor_sync(0xffffffffu, cm1, 1));
        cm1 = fmaxf(cm1, __shfl_xor_sync(0xffffffffu, cm1, 2));
        float nm0 = fmaxf(rm0, cm0), nm1 = fmaxf(rm1, cm1);
        float scl0 = ex2(rm0 - nm0), scl1 = ex2(rm1 - nm1);
        rm0 = nm0; rm1 = nm1;
        rs0 *= scl0; rs1 *= scl1;

        unsigned pa[4][4];
        float s0a = 0.f, s1a = 0.f;
#pragma unroll
        for (int kt2 = 0; kt2 < 4; kt2++) {
            float e00 = ex2(sc[2 * kt2][0] - nm0);
            float e01 = ex2(sc[2 * kt2][1] - nm0);
            float e02 = ex2(sc[2 * kt2][2] - nm1);
            float e03 = ex2(sc[2 * kt2][3] - nm1);
            float e10 = ex2(sc[2 * kt2 + 1][0] - nm0);
            float e11 = ex2(sc[2 * kt2 + 1][1] - nm0);
            float e12 = ex2(sc[2 * kt2 + 1][2] - nm1);
            float e13 = ex2(sc[2 * kt2 + 1][3] - nm1);
            pa[kt2][0] = bf2u(e00, e01);
            pa[kt2][1] = bf2u(e02, e03);
            pa[kt2][2] = bf2u(e10, e11);
            pa[kt2][3] = bf2u(e12, e13);
            s0a += e00 + e01 + e10 + e11;
            s1a += e02 + e03 + e12 + e13;
        }
        rs0 += s0a; rs1 += s1a;

#pragma unroll
        for (int ct = 0; ct < 16; ct++) {
            o[ct][0] *= scl0; o[ct][1] *= scl0;
            o[ct][2] *= scl1; o[ct][3] *= scl1;
        }

        // ---- GEMM2: O[16m][128c] += P . V^T ----
#pragma unroll
        for (int kt2 = 0; kt2 < 4; kt2++)
#pragma unroll
            for (int cg2 = 0; cg2 < 8; cg2++) {
                unsigned b00, b01, b10, b11;
                unsigned addr = smem_u32(Vs + (cg2 * 16 + (sel >> 1) * 8 + q) * 72 +
                                         kt2 * 16 + (sel & 1) * 8);
                ldsm_x4(b00, b01, b10, b11, addr);
                mma_bf16(o[cg2 * 2],     pa[kt2][0], pa[kt2][1], pa[kt2][2], pa[kt2][3], b00, b01);
                mma_bf16(o[cg2 * 2 + 1], pa[kt2][0], pa[kt2][1], pa[kt2][2], pa[kt2][3], b10, b11);
            }
        __syncthreads();
    }

    // ---- normalize + store bf16 O[m][c] ----
    rs0 += __shfl_xor_sync(0xffffffffu, rs0, 1);
    rs0 += __shfl_xor_sync(0xffffffffu, rs0, 2);
    rs1 += __shfl_xor_sync(0xffffffffu, rs1, 1);
    rs1 += __shfl_xor_sync(0xffffffffu, rs1, 2);
    float inv0 = 1.f / rs0, inv1 = 1.f / rs1;

    __nv_bfloat16* oB = d_Ot + (size_t)b * 524288;
    int row0 = m0 + wid * 16 + g;
#pragma unroll
    for (int ct = 0; ct < 16; ct++) {
        int cc = ct * 8 + 2 * t4;
        *(__nv_bfloat162*)(oB + (size_t)row0 * 128 + cc) =
            __floats2bfloat162_rn(o[ct][0] * inv0, o[ct][1] * inv0);
        *(__nv_bfloat162*)(oB + (size_t)(row0 + 8) * 128 + cc) =
            __floats2bfloat162_rn(o[ct][2] * inv1, o[ct][3] * inv1);
    }
}

// ---------------------------------------------------------------------------
// conv4 v4: R12 mainloop (C[128 oc][128 m], K=128, two-group cp.async
// pipeline) + coalesced epilogue: fragments -> fp32 smem tile (gamma/bias
// applied) -> warp-per-row float4 streams of x/out at 100% sector efficiency.
// Dynamic smem: mainloop buf0 [0,36864), buf1 [36864,73728);
// epilogue overlays Osm fp32 [128][132] = 67584 B.
// ---------------------------------------------------------------------------
__global__ void __launch_bounds__(256) conv4_kernel(
    const float* __restrict__ x, const float* __restrict__ gamma,
    float* __restrict__ out)
{
    extern __shared__ __align__(16) char smd[];
    __nv_bfloat16* Otb[2] = { (__nv_bfloat16*)smd,
                              (__nv_bfloat16*)(smd + 36864) };
    __nv_bfloat16* W4b[2] = { (__nv_bfloat16*)(smd + 18432),
                              (__nv_bfloat16*)(smd + 55296) };
    float* Osm = (float*)smd;  // epilogue overlay [128][132] fp32

    const int b = blockIdx.z, OC0 = blockIdx.y * 128, pos0 = blockIdx.x * 128;
    const int t = threadIdx.x;
    const int lane = t & 31, wid = t >> 5;
    const int g = lane >> 2, t4 = lane & 3;
    const int q = lane & 7, sel = lane >> 3;
    const int oc0w = (wid & 3) * 32, m0w = (wid >> 2) * 64;

    const __nv_bfloat16* oB = d_Ot + ((size_t)b * 4096 + pos0) * 128;

    // prefetch both K-chunks in separate groups
#pragma unroll
    for (int kh = 0; kh < 2; kh++) {
        int row = t >> 1, cq = (t & 1) * 32;
        const __nv_bfloat16* osrc = oB + (size_t)row * 128 + kh * 64 + cq;
        const __nv_bfloat16* wsrc = d_W4h + (size_t)(OC0 + row) * 128 + kh * 64 + cq;
#pragma unroll
        for (int j = 0; j < 4; j++) {
            cp16(Otb[kh] + row * 72 + cq + j * 8, osrc + j * 8);
            cp16(W4b[kh] + row * 72 + cq + j * 8, wsrc + j * 8);
        }
        cp_commit();
    }

    float c[2][8][4];
#pragma unroll
    for (int i = 0; i < 2; i++)
#pragma unroll
        for (int j = 0; j < 8; j++)
#pragma unroll
            for (int e = 0; e < 4; e++) c[i][j][e] = 0.f;

#pragma unroll
    for (int kh = 0; kh < 2; kh++) {
        if (kh == 0) cp_wait1(); else cp_wait0();
        __syncthreads();
        const __nv_bfloat16* Ots = Otb[kh];
        const __nv_bfloat16* W4s = W4b[kh];

#pragma unroll
        for (int ks = 0; ks < 4; ks++) {
            int k0 = ks * 16;
            unsigned a[2][4];
#pragma unroll
            for (int mt = 0; mt < 2; mt++) {
                unsigned addr = smem_u32(W4s + (oc0w + mt * 16 + (lane & 15)) * 72 +
                                         k0 + ((lane >> 4) << 3));
                ldsm_x4(a[mt][0], a[mt][1], a[mt][2], a[mt][3], addr);
            }
#pragma unroll
            for (int mgp = 0; mgp < 4; mgp++) {
                unsigned b00, b01, b10, b11;
                unsigned addr = smem_u32(Ots + (m0w + mgp * 16 + (sel >> 1) * 8 + q) * 72 +
                                         k0 + (sel & 1) * 8);
                ldsm_x4(b00, b01, b10, b11, addr);
                mma_bf16(c[0][mgp * 2],     a[0][0], a[0][1], a[0][2], a[0][3], b00, b01);
                mma_bf16(c[0][mgp * 2 + 1], a[0][0], a[0][1], a[0][2], a[0][3], b10, b11);
                mma_bf16(c[1][mgp * 2],     a[1][0], a[1][1], a[1][2], a[1][3], b00, b01);
                mma_bf16(c[1][mgp * 2 + 1], a[1][0], a[1][1], a[1][2], a[1][3], b10, b11);
            }
        }
    }
    __syncthreads();  // mainloop smem reads done; Osm overlay now safe

    // ---- fragments -> Osm (gamma & bias applied) ----
    float gm = *gamma;
#pragma unroll
    for (int mt = 0; mt < 2; mt++) {
        int ocl = oc0w + mt * 16 + g;
        float bA = d_B4[OC0 + ocl];
        float bB = d_B4[OC0 + ocl + 8];
#pragma unroll
        for (int nt = 0; nt < 8; nt++) {
            int m = m0w + nt * 8 + 2 * t4;
            float2 ra;
            ra.x = gm * (c[mt][nt][0] + bA);
            ra.y = gm * (c[mt][nt][1] + bA);
            *(float2*)&Osm[ocl * 132 + m] = ra;
            float2 rb;
            rb.x = gm * (c[mt][nt][2] + bB);
            rb.y = gm * (c[mt][nt][3] + bB);
            *(float2*)&Osm[(ocl + 8) * 132 + m] = rb;
        }
    }
    __syncthreads();

    // ---- coalesced residual + store: warp per oc-row, float4 streams ----
#pragma unroll
    for (int rr = 0; rr < 16; rr++) {
        int row = wid * 16 + rr;
        size_t gbase = (size_t)b * 1048576 + (size_t)(OC0 + row) * 4096 + pos0;
        float4 xv = *(const float4*)(x + gbase + lane * 4);
        float4 ov = *(const float4*)&Osm[row * 132 + lane * 4];
        ov.x += xv.x; ov.y += xv.y; ov.z += xv.z; ov.w += xv.w;
        *(float4*)(out + gbase + lane * 4) = ov;
    }
}

// ---------------------------------------------------------------------------
extern "C" void kernel_launch(void* const* d_in, const int* in_sizes, int n_in,
                              void* d_out, int out_size)
{
    const float* x = (const float*)d_in[0];
    const float* w1 = (const float*)d_in[1];
    const float* b1 = (const float*)d_in[2];
    const float* s1 = (const float*)d_in[3];
    const float* t1 = (const float*)d_in[4];
    const float* m1 = (const float*)d_in[5];
    const float* v1 = (const float*)d_in[6];
    const float* w2 = (const float*)d_in[7];
    const float* b2 = (const float*)d_in[8];
    const float* s2 = (const float*)d_in[9];
    const float* t2 = (const float*)d_in[10];
    const float* m2 = (const float*)d_in[11];
    const float* v2 = (const float*)d_in[12];
    const float* w3 = (const float*)d_in[13];
    const float* b3 = (const float*)d_in[14];
    const float* s3 = (const float*)d_in[15];
    const float* t3 = (const float*)d_in[16];
    const float* m3 = (const float*)d_in[17];
    const float* v3 = (const float*)d_in[18];
    const float* w4 = (const float*)d_in[19];
    const float* b4 = (const float*)d_in[20];
    const float* s4 = (const float*)d_in[21];
    const float* t4 = (const float*)d_in[22];
    const float* m4 = (const float*)d_in[23];
    const float* v4 = (const float*)d_in[24];
    const float* gamma = (const float*)d_in[25];

    cudaFuncSetAttribute(attn_kernel,
                         cudaFuncAttributeMaxDynamicSharedMemorySize, 57344);
    cudaFuncSetAttribute(conv4_kernel,
                         cudaFuncAttributeMaxDynamicSharedMemorySize, 73728);

    prep_kernel<<<22, 256>>>(w1, b1, s1, t1, m1, v1,
                             w2, b2, s2, t2, m2, v2,
                             w3, b3, s3, t3, m3, v3,
                             w4, b4, s4, t4, m4, v4);
    conv123_kernel<<<dim3(32, 8), 512>>>(x);
    attn_kernel<<<dim3(32, 8), 256, 57344>>>();
    conv4_kernel<<<dim3(32, 2, 8), 256, 73728>>>(x, gamma, (float*)d_out);
}